// round 11
// baseline (speedup 1.0000x reference)
#include <cuda_runtime.h>
#include <cstdint>

#define CTA_THREADS 128
#define PAIRS_PER_CTA 2

// ---- smem layout (u32 units) ----
#define OFF_W2T   0
#define W2T_U32   1152                 // W2 transposed [72][16] fp32
#define XS_U32    842                  // xs bf16x2[29][29] + pad
#define Z1_U32    1920                 // z1 bf16x2[8][15][16]
#define PAIR_U32  (XS_U32 + Z1_U32)    // 2762
#define OFF_PART  (W2T_U32 + PAIRS_PER_CTA * PAIR_U32)   // 6676
#define SMEM_U32  (OFF_PART + 8)       // 6684
#define SMEM_BYTES (SMEM_U32 * 4)      // 26736 B

__device__ __forceinline__ float2 ffma2(float2 a, float2 b, float2 c) {
    unsigned long long ua = *reinterpret_cast<unsigned long long*>(&a);
    unsigned long long ub = *reinterpret_cast<unsigned long long*>(&b);
    unsigned long long uc = *reinterpret_cast<unsigned long long*>(&c);
    unsigned long long ud;
    asm("fma.rn.f32x2 %0, %1, %2, %3;" : "=l"(ud) : "l"(ua), "l"(ub), "l"(uc));
    return *reinterpret_cast<float2*>(&ud);
}
__device__ __forceinline__ float2 bcast2(float v) { return make_float2(v, v); }

__device__ __forceinline__ uint32_t pack_bf2(float lo, float hi) {
    uint32_t r;
    asm("cvt.rn.satfinite.bf16x2.f32 %0, %1, %2;" : "=r"(r) : "f"(hi), "f"(lo));
    return r;
}
__device__ __forceinline__ float2 unpack_bf2(uint32_t u) {
    float2 f;
    f.x = __uint_as_float(u << 16);
    f.y = __uint_as_float(u & 0xFFFF0000u);
    return f;
}

__device__ __forceinline__ float finish_prob(float z) {
    float sp = fmaxf(z, 0.0f) + log1pf(expf(-fabsf(z)));
    float r  = sp + 0.001f;
    float pr = -expm1f(-r);
    return fminf(fmaxf(pr, 1e-6f), 1.0f - 1e-6f);
}

// conv2 over NT pixel slots starting at t=TBASE, all 16 output channels in
// groups of 4 (cg), then the FC partial for those slots. acc[och][slot].
template<int NT, int TBASE>
__device__ __forceinline__ float2 conv2_fc(const uint32_t* __restrict__ z1s,
                                           const float4*  __restrict__ W2T4,
                                           const float*   __restrict__ b2,
                                           const float*   __restrict__ Wfc,
                                           int cg, int ps) {
    const int cb = 4 * cg;
    int boff[NT];
    #pragma unroll
    for (int tt = 0; tt < NT; tt++) {
        int p = ps + 8 * (TBASE + tt);
        int pe = p < 49 ? p : 48;
        int i = pe / 7, j = pe - i * 7;
        boff[tt] = (2 * i) * 16 + 2 * j;
    }

    float2 acc[4][NT];
    #pragma unroll
    for (int cc = 0; cc < 4; cc++) {
        float bb = b2[cb + cc];
        #pragma unroll
        for (int tt = 0; tt < NT; tt++) acc[cc][tt] = bcast2(bb);
    }

    #pragma unroll 1
    for (int ci = 0; ci < 8; ci++) {
        const uint32_t* zb = z1s + ci * 240;
        const int wk = ci * 9;
        #pragma unroll
        for (int di = 0; di < 3; di++) {
            float4 wd0 = W2T4[(wk + di * 3 + 0) * 4 + cg];
            float4 wd1 = W2T4[(wk + di * 3 + 1) * 4 + cg];
            float4 wd2 = W2T4[(wk + di * 3 + 2) * 4 + cg];
            float w0[4] = {wd0.x, wd0.y, wd0.z, wd0.w};
            float w1[4] = {wd1.x, wd1.y, wd1.z, wd1.w};
            float w2[4] = {wd2.x, wd2.y, wd2.z, wd2.w};
            #pragma unroll
            for (int tt = 0; tt < NT; tt++) {
                const uint32_t* zp = zb + boff[tt] + di * 16;
                uint2 pr = *reinterpret_cast<const uint2*>(zp);
                uint32_t p2 = zp[2];
                float2 z0  = unpack_bf2(pr.x);
                float2 z1v = unpack_bf2(pr.y);
                float2 z2v = unpack_bf2(p2);
                #pragma unroll
                for (int cc = 0; cc < 4; cc++) {
                    acc[cc][tt] = ffma2(z0,  bcast2(w0[cc]), acc[cc][tt]);
                    acc[cc][tt] = ffma2(z1v, bcast2(w1[cc]), acc[cc][tt]);
                    acc[cc][tt] = ffma2(z2v, bcast2(w2[cc]), acc[cc][tt]);
                }
            }
        }
    }

    float2 part = make_float2(0.f, 0.f);
    #pragma unroll
    for (int cc = 0; cc < 4; cc++)
        #pragma unroll
        for (int tt = 0; tt < NT; tt++) {
            int p = ps + 8 * (TBASE + tt);
            if (p < 49) {
                float wf = Wfc[(cb + cc) * 49 + p];
                float2 rz = make_float2(fmaxf(acc[cc][tt].x, 0.f),
                                        fmaxf(acc[cc][tt].y, 0.f));
                part = ffma2(rz, bcast2(wf), part);
            }
        }
    return part;
}

__global__ __launch_bounds__(CTA_THREADS, 6)
void diffsol_fused_kernel(const float* __restrict__ x,
                          const float* __restrict__ W1,
                          const float* __restrict__ b1,
                          const float* __restrict__ W2,
                          const float* __restrict__ b2,
                          const float* __restrict__ Wfc,
                          const float* __restrict__ bfc,
                          float* __restrict__ out,
                          int npairs) {
    extern __shared__ uint32_t smem[];
    float* sW2t = reinterpret_cast<float*>(smem + OFF_W2T);

    const int tid = threadIdx.x;
    for (int i = tid; i < 1152; i += CTA_THREADS)
        sW2t[(i % 72) * 16 + (i / 72)] = W2[i];

    const int warp = tid >> 5;
    const int lane = tid & 31;
    const int pair = warp >> 1;     // 0..1
    const int role = warp & 1;      // 0..1 (two warps cooperate on one pair)
    const int g = blockIdx.x * PAIRS_PER_CTA + pair;
    const bool active = g < npairs;

    uint32_t* pb  = smem + W2T_U32 + pair * PAIR_U32;
    uint32_t* xs  = pb;             // [29][29] bf16x2, zero-pad top/left
    uint32_t* z1s = pb + XS_U32;    // [8][15][16] bf16x2, zero-pad row0/col0

    // ---- stage input pair (both warps of the pair, stride 64) ----
    if (active) {
        const float* x0 = x + (size_t)(2 * g) * 784;
        const float* x1 = x0 + 784;
        const int idx = role * 32 + lane;   // 0..63
        for (int e = idx; e < 784; e += 64) {
            int r = e / 28, c = e - r * 28;
            xs[(r + 1) * 29 + (c + 1)] = pack_bf2(x0[e], x1[e]);
        }
        if (idx < 57) {
            if (idx < 29) xs[idx] = 0u;
            else          xs[(idx - 28) * 29] = 0u;
        }
        for (int z = idx; z < 240; z += 64) {   // z1 pads: 8ch * (16 + 14)
            int ch = z / 30, q = z - ch * 30;
            if (q < 16) z1s[ch * 240 + q] = 0u;
            else        z1s[ch * 240 + (q - 15) * 16] = 0u;
        }
    }
    __syncthreads();

    // ---- conv1: each warp computes 4 z1 channels; lane = pixel, 7 iters ----
    if (active) {
        const int c0 = 4 * role;
        float w1r[4][9], b1r[4];
        #pragma unroll
        for (int cc = 0; cc < 4; cc++) {
            b1r[cc] = b1[c0 + cc];
            #pragma unroll
            for (int k = 0; k < 9; k++) w1r[cc][k] = W1[(c0 + cc) * 9 + k];
        }

        #pragma unroll 1
        for (int t = 0; t < 7; t++) {
            int p = lane + 32 * t;
            int pe = p < 196 ? p : 195;
            int i = pe / 14, j = pe - i * 14;
            const uint32_t* xb = xs + (2 * i) * 29 + 2 * j;
            float2 a[4];
            #pragma unroll
            for (int cc = 0; cc < 4; cc++) a[cc] = bcast2(b1r[cc]);
            #pragma unroll
            for (int di = 0; di < 3; di++)
                #pragma unroll
                for (int dj = 0; dj < 3; dj++) {
                    float2 xv = unpack_bf2(xb[di * 29 + dj]);
                    #pragma unroll
                    for (int cc = 0; cc < 4; cc++)
                        a[cc] = ffma2(xv, bcast2(w1r[cc][di * 3 + dj]), a[cc]);
                }
            if (p < 196) {
                #pragma unroll
                for (int cc = 0; cc < 4; cc++) {
                    float lo = fmaxf(a[cc].x, 0.f);
                    float hi = fmaxf(a[cc].y, 0.f);
                    z1s[(c0 + cc) * 240 + (i + 1) * 16 + (j + 1)] = pack_bf2(lo, hi);
                }
            }
        }
    }
    __syncthreads();

    // ---- conv2 + FC partial: role 0 -> slots t 0..3, role 1 -> t 4..6 ----
    if (active) {
        const int cg = lane >> 3;
        const int ps = lane & 7;
        const float4* W2T4 = reinterpret_cast<const float4*>(sW2t);

        float2 part = (role == 0)
            ? conv2_fc<4, 0>(z1s, W2T4, b2, Wfc, cg, ps)
            : conv2_fc<3, 4>(z1s, W2T4, b2, Wfc, cg, ps);

        #pragma unroll
        for (int off = 16; off; off >>= 1) {
            part.x += __shfl_xor_sync(0xffffffffu, part.x, off);
            part.y += __shfl_xor_sync(0xffffffffu, part.y, off);
        }
        if (lane == 0) {
            float2* sp = reinterpret_cast<float2*>(smem + OFF_PART);
            sp[pair * 2 + role] = part;
        }
    }
    __syncthreads();

    if (active && role == 0 && lane == 0) {
        const float2* sp = reinterpret_cast<const float2*>(smem + OFF_PART);
        float2 pa = sp[pair * 2 + 0];
        float2 pb2 = sp[pair * 2 + 1];
        float bb = bfc[0];
        out[2 * g]     = finish_prob(pa.x + pb2.x + bb);
        out[2 * g + 1] = finish_prob(pa.y + pb2.y + bb);
    }
}

extern "C" void kernel_launch(void* const* d_in, const int* in_sizes, int n_in,
                              void* d_out, int out_size) {
    const float* x   = (const float*)d_in[0];
    const float* W1  = (const float*)d_in[1];
    const float* b1  = (const float*)d_in[2];
    const float* W2  = (const float*)d_in[3];
    const float* b2  = (const float*)d_in[4];
    const float* Wfc = (const float*)d_in[5];
    const float* bfc = (const float*)d_in[6];
    float* out = (float*)d_out;

    int nimg = in_sizes[0] / 784;
    int npairs = nimg / 2;
    int ctas = (npairs + PAIRS_PER_CTA - 1) / PAIRS_PER_CTA;

    cudaFuncSetAttribute(diffsol_fused_kernel,
                         cudaFuncAttributeMaxDynamicSharedMemorySize, SMEM_BYTES);
    diffsol_fused_kernel<<<ctas, CTA_THREADS, SMEM_BYTES>>>(
        x, W1, b1, W2, b2, Wfc, bfc, out, npairs);
}